// round 1
// baseline (speedup 1.0000x reference)
#include <cuda_runtime.h>
#include <cuda_bf16.h>
#include <math.h>

// ---------------- problem constants ----------------
#define NNODES 8192
#define NEDGES 65536
#define DIN    768
#define DHID   768
#define H1N    8
#define H2N    1
#define NEG_SLOPE 0.2f
#define EPSV 1e-16f

// ---------------- scratch (device globals; no allocs allowed) ----------------
__device__ float g_h1[(size_t)NNODES * (H1N * DHID)];   // x @ W1            [N, 6144]
__device__ float g_o1[(size_t)NNODES * (H1N * DHID)];   // elu(agg1 + b1)    [N, 6144]
__device__ float g_h2[(size_t)NNODES * DHID];           // o1 @ W2           [N, 768]
__device__ float g_as1[NNODES * H1N];
__device__ float g_ad1[NNODES * H1N];
__device__ float g_as2[NNODES * H2N];
__device__ float g_ad2[NNODES * H2N];
__device__ float g_alpha1[(size_t)NEDGES * H1N];
__device__ float g_alpha2[(size_t)NEDGES * H2N];
__device__ int   g_deg[NNODES];
__device__ int   g_cur[NNODES];
__device__ int   g_off[NNODES + 1];
__device__ int   g_eid[NEDGES];

// ---------------- CSR build ----------------
__global__ void zero_counts_kernel() {
    int i = blockIdx.x * blockDim.x + threadIdx.x;
    if (i < NNODES) { g_deg[i] = 0; g_cur[i] = 0; }
}

__global__ void count_kernel(const int* __restrict__ dst) {
    int e = blockIdx.x * blockDim.x + threadIdx.x;
    if (e < NEDGES) atomicAdd(&g_deg[dst[e]], 1);
}

// exclusive scan of g_deg (8192) -> g_off. single block, 1024 threads x 8 elems.
__global__ void scan_kernel() {
    __shared__ int s[1024];
    int t = threadIdx.x;
    int base = t * 8;
    int local[8];
    int run = 0;
#pragma unroll
    for (int i = 0; i < 8; i++) { local[i] = run; run += g_deg[base + i]; }
    s[t] = run;
    __syncthreads();
    for (int o = 1; o < 1024; o <<= 1) {
        int v = (t >= o) ? s[t - o] : 0;
        __syncthreads();
        s[t] += v;
        __syncthreads();
    }
    int prev = (t == 0) ? 0 : s[t - 1];
#pragma unroll
    for (int i = 0; i < 8; i++) g_off[base + i] = prev + local[i];
    if (t == 1023) g_off[NNODES] = s[1023];
}

__global__ void scatter_kernel(const int* __restrict__ dst) {
    int e = blockIdx.x * blockDim.x + threadIdx.x;
    if (e < NEDGES) {
        int d = dst[e];
        int p = atomicAdd(&g_cur[d], 1);
        g_eid[g_off[d] + p] = e;
    }
}

// ---------------- SGEMM: C[M,N] = A[M,K] @ B[K,N], row-major, dims divisible ----------------
#define BM 128
#define BN 128
#define BK 16
#define TM 8
#define TN 8

__global__ void __launch_bounds__(256)
sgemm_kernel(const float* __restrict__ A, const float* __restrict__ B,
             float* __restrict__ C, int M, int N, int K)
{
    __shared__ float As[BK][BM];
    __shared__ float Bs[BK][BN];

    const int tid = threadIdx.x;
    const int tx = tid % (BN / TN);   // 0..15
    const int ty = tid / (BN / TN);   // 0..15
    const int bx = blockIdx.x;        // N tile
    const int by = blockIdx.y;        // M tile

    const float* Aptr = A + (size_t)by * BM * K;
    const float* Bptr = B + (size_t)bx * BN;

    const int aRow = tid >> 2;          // 0..63
    const int aCol = (tid & 3) * 4;     // 0,4,8,12
    const int bRow = tid >> 5;          // 0..7
    const int bCol = (tid & 31) * 4;    // 0..124

    float acc[TM][TN] = {};

    for (int k0 = 0; k0 < K; k0 += BK) {
#pragma unroll
        for (int r = 0; r < 2; r++) {
            float4 v = *(const float4*)(Aptr + (size_t)(aRow + r * 64) * K + k0 + aCol);
            As[aCol + 0][aRow + r * 64] = v.x;
            As[aCol + 1][aRow + r * 64] = v.y;
            As[aCol + 2][aRow + r * 64] = v.z;
            As[aCol + 3][aRow + r * 64] = v.w;
        }
#pragma unroll
        for (int r = 0; r < 2; r++) {
            float4 v = *(const float4*)(Bptr + (size_t)(k0 + bRow + r * 8) * N + bCol);
            *(float4*)&Bs[bRow + r * 8][bCol] = v;
        }
        __syncthreads();

#pragma unroll
        for (int kk = 0; kk < BK; kk++) {
            float a_frag[TM], b_frag[TN];
            float4 a0 = *(const float4*)&As[kk][ty * TM];
            float4 a1 = *(const float4*)&As[kk][ty * TM + 4];
            float4 b0 = *(const float4*)&Bs[kk][tx * TN];
            float4 b1 = *(const float4*)&Bs[kk][tx * TN + 4];
            a_frag[0] = a0.x; a_frag[1] = a0.y; a_frag[2] = a0.z; a_frag[3] = a0.w;
            a_frag[4] = a1.x; a_frag[5] = a1.y; a_frag[6] = a1.z; a_frag[7] = a1.w;
            b_frag[0] = b0.x; b_frag[1] = b0.y; b_frag[2] = b0.z; b_frag[3] = b0.w;
            b_frag[4] = b1.x; b_frag[5] = b1.y; b_frag[6] = b1.z; b_frag[7] = b1.w;
#pragma unroll
            for (int i = 0; i < TM; i++)
#pragma unroll
                for (int j = 0; j < TN; j++)
                    acc[i][j] += a_frag[i] * b_frag[j];
        }
        __syncthreads();
    }

    float* Cptr = C + (size_t)(by * BM + ty * TM) * N + bx * BN + tx * TN;
#pragma unroll
    for (int i = 0; i < TM; i++) {
#pragma unroll
        for (int j = 0; j < TN; j += 4) {
            float4 v = make_float4(acc[i][j], acc[i][j + 1], acc[i][j + 2], acc[i][j + 3]);
            *(float4*)(Cptr + (size_t)i * N + j) = v;
        }
    }
}

// ---------------- per-(node,head) attention coefficients: alpha_s/alpha_d dots ----------------
__global__ void alphas_kernel(const float* __restrict__ h,
                              const float* __restrict__ a_s, const float* __restrict__ a_d,
                              float* __restrict__ out_s, float* __restrict__ out_d,
                              int H, int C)
{
    int w = (blockIdx.x * blockDim.x + threadIdx.x) >> 5;
    int lane = threadIdx.x & 31;
    if (w >= NNODES * H) return;
    int n = w / H, hd = w % H;
    const float* hp  = h + (size_t)n * H * C + (size_t)hd * C;
    const float* asp = a_s + (size_t)hd * C;
    const float* adp = a_d + (size_t)hd * C;
    float ss = 0.f, sd = 0.f;
    for (int c = lane; c < C; c += 32) {
        float v = hp[c];
        ss += v * asp[c];
        sd += v * adp[c];
    }
#pragma unroll
    for (int o = 16; o; o >>= 1) {
        ss += __shfl_down_sync(0xffffffffu, ss, o);
        sd += __shfl_down_sync(0xffffffffu, sd, o);
    }
    if (lane == 0) { out_s[w] = ss; out_d[w] = sd; }
}

// ---------------- per-(dst,head) segment softmax over incoming edges ----------------
__global__ void softmax_kernel(const int* __restrict__ src,
                               const float* __restrict__ as, const float* __restrict__ ad,
                               float* __restrict__ alpha, int H)
{
    int idx = blockIdx.x * blockDim.x + threadIdx.x;
    if (idx >= NNODES * H) return;
    int d = idx / H, hd = idx % H;
    int s0 = g_off[d], s1 = g_off[d + 1];
    if (s0 == s1) return;
    float adv = ad[idx];

    float m = -1e30f;
    for (int i = s0; i < s1; i++) {
        int e = g_eid[i];
        float x = as[src[e] * H + hd] + adv;
        x = (x > 0.f) ? x : NEG_SLOPE * x;
        m = fmaxf(m, x);
    }
    float sum = 0.f;
    for (int i = s0; i < s1; i++) {
        int e = g_eid[i];
        float x = as[src[e] * H + hd] + adv;
        x = (x > 0.f) ? x : NEG_SLOPE * x;
        float w = __expf(x - m);
        alpha[(size_t)e * H + hd] = w;
        sum += w;
    }
    float inv = 1.f / (sum + EPSV);
    for (int i = s0; i < s1; i++) {
        int e = g_eid[i];
        alpha[(size_t)e * H + hd] *= inv;
    }
}

// ---------------- aggregation: out[d, hd*C:] = act( sum_e alpha * h[src] + b ) ----------------
// grid = N*H blocks, block = C/4 threads (192), float4 per thread.
__global__ void __launch_bounds__(192)
aggregate_kernel(const int* __restrict__ src, const float* __restrict__ alpha,
                 const float* __restrict__ h, float* __restrict__ out,
                 const float* __restrict__ bias, int H, int C, int do_elu)
{
    int d  = blockIdx.x / H;
    int hd = blockIdx.x % H;
    int t  = threadIdx.x;
    int s0 = g_off[d], s1 = g_off[d + 1];
    size_t rs = (size_t)H * C;

    float4 acc = make_float4(0.f, 0.f, 0.f, 0.f);
    for (int i = s0; i < s1; i++) {
        int e = g_eid[i];
        float a = alpha[(size_t)e * H + hd];
        float4 v = *(((const float4*)(h + (size_t)src[e] * rs + (size_t)hd * C)) + t);
        acc.x += a * v.x; acc.y += a * v.y; acc.z += a * v.z; acc.w += a * v.w;
    }
    float4 b = *(((const float4*)(bias + (size_t)hd * C)) + t);
    acc.x += b.x; acc.y += b.y; acc.z += b.z; acc.w += b.w;
    if (do_elu) {
        acc.x = (acc.x > 0.f) ? acc.x : expm1f(acc.x);
        acc.y = (acc.y > 0.f) ? acc.y : expm1f(acc.y);
        acc.z = (acc.z > 0.f) ? acc.z : expm1f(acc.z);
        acc.w = (acc.w > 0.f) ? acc.w : expm1f(acc.w);
    }
    *(((float4*)(out + (size_t)d * rs + (size_t)hd * C)) + t) = acc;
}

// ---------------- launch ----------------
extern "C" void kernel_launch(void* const* d_in, const int* in_sizes, int n_in,
                              void* d_out, int out_size)
{
    const float* x    = (const float*)d_in[0];
    const float* W1   = (const float*)d_in[1];
    const float* a_s1 = (const float*)d_in[2];
    const float* a_d1 = (const float*)d_in[3];
    const float* b1   = (const float*)d_in[4];
    const float* W2   = (const float*)d_in[5];
    const float* a_s2 = (const float*)d_in[6];
    const float* a_d2 = (const float*)d_in[7];
    const float* b2   = (const float*)d_in[8];
    const int* edges  = (const int*)d_in[9];
    const int* src = edges;
    const int* dst = edges + NEDGES;
    float* out = (float*)d_out;

    float *h1, *o1, *h2, *as1, *ad1, *as2, *ad2, *al1, *al2;
    cudaGetSymbolAddress((void**)&h1,  g_h1);
    cudaGetSymbolAddress((void**)&o1,  g_o1);
    cudaGetSymbolAddress((void**)&h2,  g_h2);
    cudaGetSymbolAddress((void**)&as1, g_as1);
    cudaGetSymbolAddress((void**)&ad1, g_ad1);
    cudaGetSymbolAddress((void**)&as2, g_as2);
    cudaGetSymbolAddress((void**)&ad2, g_ad2);
    cudaGetSymbolAddress((void**)&al1, g_alpha1);
    cudaGetSymbolAddress((void**)&al2, g_alpha2);

    // ---- CSR by destination (shared by both layers) ----
    zero_counts_kernel<<<(NNODES + 255) / 256, 256>>>();
    count_kernel<<<(NEDGES + 255) / 256, 256>>>(dst);
    scan_kernel<<<1, 1024>>>();
    scatter_kernel<<<(NEDGES + 255) / 256, 256>>>(dst);

    // ---- layer 1 ----
    {
        dim3 grid((H1N * DHID) / BN, NNODES / BM);   // (48, 64)
        sgemm_kernel<<<grid, 256>>>(x, W1, h1, NNODES, H1N * DHID, DIN);
    }
    {
        int warps = NNODES * H1N;
        alphas_kernel<<<(warps * 32 + 255) / 256, 256>>>(h1, a_s1, a_d1, as1, ad1, H1N, DHID);
    }
    softmax_kernel<<<(NNODES * H1N + 255) / 256, 256>>>(src, as1, ad1, al1, H1N);
    aggregate_kernel<<<NNODES * H1N, DHID / 4>>>(src, al1, h1, o1, b1, H1N, DHID, 1);

    // ---- layer 2 ----
    {
        dim3 grid((H2N * DHID) / BN, NNODES / BM);   // (6, 64)
        sgemm_kernel<<<grid, 256>>>(o1, W2, h2, NNODES, H2N * DHID, H1N * DHID);
    }
    {
        int warps = NNODES * H2N;
        alphas_kernel<<<(warps * 32 + 255) / 256, 256>>>(h2, a_s2, a_d2, as2, ad2, H2N, DHID);
    }
    softmax_kernel<<<(NNODES * H2N + 255) / 256, 256>>>(src, as2, ad2, al2, H2N);
    aggregate_kernel<<<NNODES * H2N, DHID / 4>>>(src, al2, h2, out, b2, H2N, DHID, 0);
}

// round 2
// speedup vs baseline: 2.6017x; 2.6017x over previous
#include <cuda_runtime.h>
#include <cuda_bf16.h>
#include <math.h>

// ---------------- problem constants ----------------
#define NNODES 8192
#define NEDGES 65536
#define DIN    768
#define DHID   768
#define H1N    8
#define H2N    1
#define NEG_SLOPE 0.2f
#define EPSV 1e-16f

// ---------------- scratch (device globals; no allocs allowed) ----------------
__device__ float g_h1[(size_t)NNODES * (H1N * DHID)];   // x @ W1            [N, 6144]
__device__ float g_o1[(size_t)NNODES * (H1N * DHID)];   // elu(agg1 + b1), tf32-rounded
__device__ float g_h2[(size_t)NNODES * DHID];           // o1 @ W2           [N, 768]
__device__ float g_xr [(size_t)NNODES * DIN];           // tf32-rounded x
__device__ float g_w1r[(size_t)DIN * (H1N * DHID)];     // tf32-rounded W1
__device__ float g_w2r[(size_t)(H1N * DHID) * DHID];    // tf32-rounded W2
__device__ float g_as1[NNODES * H1N];
__device__ float g_ad1[NNODES * H1N];
__device__ float g_as2[NNODES * H2N];
__device__ float g_ad2[NNODES * H2N];
__device__ float g_alpha1[(size_t)NEDGES * H1N];
__device__ float g_alpha2[(size_t)NEDGES * H2N];
__device__ int   g_deg[NNODES];
__device__ int   g_cur[NNODES];
__device__ int   g_off[NNODES + 1];
__device__ int   g_eid[NEDGES];

// ---------------- helpers ----------------
__device__ __forceinline__ float tf32r(float x) {
    unsigned u;
    asm("cvt.rna.tf32.f32 %0, %1;" : "=r"(u) : "f"(x));
    return __uint_as_float(u);
}

__device__ __forceinline__ void cp16(unsigned dst, const void* src) {
    asm volatile("cp.async.cg.shared.global [%0], [%1], 16;" :: "r"(dst), "l"(src));
}

#define MMA_TF32(d, a, b)                                                              \
    asm volatile(                                                                      \
        "mma.sync.aligned.m16n8k8.row.col.f32.tf32.tf32.f32 "                          \
        "{%0,%1,%2,%3},{%4,%5,%6,%7},{%8,%9},{%0,%1,%2,%3};"                           \
        : "+f"(d[0]), "+f"(d[1]), "+f"(d[2]), "+f"(d[3])                               \
        : "r"(a[0]), "r"(a[1]), "r"(a[2]), "r"(a[3]), "r"(b[0]), "r"(b[1]))

// ---------------- tf32 round-copy ----------------
__global__ void round_tf32_kernel(const float* __restrict__ in, float* __restrict__ out, int n4) {
    int i = blockIdx.x * blockDim.x + threadIdx.x;
    if (i < n4) {
        float4 v = ((const float4*)in)[i];
        v.x = tf32r(v.x); v.y = tf32r(v.y); v.z = tf32r(v.z); v.w = tf32r(v.w);
        ((float4*)out)[i] = v;
    }
}

// ---------------- CSR build ----------------
__global__ void zero_counts_kernel() {
    int i = blockIdx.x * blockDim.x + threadIdx.x;
    if (i < NNODES) { g_deg[i] = 0; g_cur[i] = 0; }
}

__global__ void count_kernel(const int* __restrict__ dst) {
    int e = blockIdx.x * blockDim.x + threadIdx.x;
    if (e < NEDGES) atomicAdd(&g_deg[dst[e]], 1);
}

__global__ void scan_kernel() {
    __shared__ int s[1024];
    int t = threadIdx.x;
    int base = t * 8;
    int local[8];
    int run = 0;
#pragma unroll
    for (int i = 0; i < 8; i++) { local[i] = run; run += g_deg[base + i]; }
    s[t] = run;
    __syncthreads();
    for (int o = 1; o < 1024; o <<= 1) {
        int v = (t >= o) ? s[t - o] : 0;
        __syncthreads();
        s[t] += v;
        __syncthreads();
    }
    int prev = (t == 0) ? 0 : s[t - 1];
#pragma unroll
    for (int i = 0; i < 8; i++) g_off[base + i] = prev + local[i];
    if (t == 1023) g_off[NNODES] = s[1023];
}

__global__ void scatter_kernel(const int* __restrict__ dst) {
    int e = blockIdx.x * blockDim.x + threadIdx.x;
    if (e < NEDGES) {
        int d = dst[e];
        int p = atomicAdd(&g_cur[d], 1);
        g_eid[g_off[d] + p] = e;
    }
}

// ---------------- TF32 tensor-core GEMM ----------------
// C[M,N] = A[M,K] @ B[K,N], row-major, M%128==0, N%128==0, K%32==0.
// Inputs must already be tf32-rounded fp32.
// Block 128x128x32, 8 warps (2x4), warp tile 64x32, double-buffered cp.async.
#define GSA 36      // As row stride (floats): 128 rows of 32 + pad 4 -> conflict-free frags
#define GSB 136     // Bs row stride (floats): 32 rows of 128 + pad 8 -> conflict-free frags
#define GASZ (128 * GSA)
#define GBSZ (32 * GSB)

__global__ void __launch_bounds__(256)
tf32_gemm(const float* __restrict__ A, const float* __restrict__ B, float* __restrict__ C,
          int M, int N, int K)
{
    extern __shared__ float smem[];
    float* As = smem;              // [2][GASZ]
    float* Bs = smem + 2 * GASZ;   // [2][GBSZ]
    unsigned as_u = (unsigned)__cvta_generic_to_shared(As);
    unsigned bs_u = (unsigned)__cvta_generic_to_shared(Bs);

    const int tid  = threadIdx.x;
    const int bn   = blockIdx.x, bm = blockIdx.y;
    const int wid  = tid >> 5, lane = tid & 31;
    const int wm   = (wid >> 2) * 64;   // warp M origin in tile
    const int wn   = (wid & 3) * 32;    // warp N origin in tile
    const int g    = lane >> 2;         // groupID 0..7
    const int tg   = lane & 3;          // thread-in-group 0..3

    // global load indexing
    const int ar = tid >> 3, ac = (tid & 7) * 4;       // A: 32 rows / wave, 4 waves
    const int brr = tid >> 5, bcv = (tid & 31) * 4;    // B: 8 rows / wave, 4 waves
    const float* Abase = A + (size_t)(bm * 128 + ar) * K + ac;
    const float* Bbase = B + (size_t)brr * N + bn * 128 + bcv;

    float acc[16][4] = {};
    const int T = K / 32;

    // prologue: tile 0 -> buf 0
    {
        unsigned ad = as_u + (unsigned)((ar * GSA + ac) * 4);
        unsigned bd = bs_u + (unsigned)((brr * GSB + bcv) * 4);
#pragma unroll
        for (int i = 0; i < 4; i++) cp16(ad + i * 32 * GSA * 4, Abase + (size_t)i * 32 * K);
#pragma unroll
        for (int i = 0; i < 4; i++) cp16(bd + i * 8 * GSB * 4, Bbase + (size_t)i * 8 * N);
        asm volatile("cp.async.commit_group;");
    }

    for (int t = 0; t < T; t++) {
        asm volatile("cp.async.wait_group 0;");
        __syncthreads();

        if (t + 1 < T) {
            int k0 = (t + 1) * 32;
            int buf = (t + 1) & 1;
            unsigned ad = as_u + (unsigned)((buf * GASZ + ar * GSA + ac) * 4);
            unsigned bd = bs_u + (unsigned)((buf * GBSZ + brr * GSB + bcv) * 4);
            const float* ap = Abase + k0;
            const float* bp = Bbase + (size_t)k0 * N;
#pragma unroll
            for (int i = 0; i < 4; i++) cp16(ad + i * 32 * GSA * 4, ap + (size_t)i * 32 * K);
#pragma unroll
            for (int i = 0; i < 4; i++) cp16(bd + i * 8 * GSB * 4, bp + (size_t)i * 8 * N);
            asm volatile("cp.async.commit_group;");
        }

        const float* Ab = As + (t & 1) * GASZ;
        const float* Bb = Bs + (t & 1) * GBSZ;
#pragma unroll
        for (int ks = 0; ks < 4; ks++) {
            unsigned a[4][4], b[4][2];
#pragma unroll
            for (int mi = 0; mi < 4; mi++) {
                const float* p = Ab + (size_t)(wm + mi * 16 + g) * GSA + ks * 8 + tg;
                a[mi][0] = __float_as_uint(p[0]);
                a[mi][1] = __float_as_uint(p[8 * GSA]);
                a[mi][2] = __float_as_uint(p[4]);
                a[mi][3] = __float_as_uint(p[8 * GSA + 4]);
            }
#pragma unroll
            for (int ni = 0; ni < 4; ni++) {
                const float* p = Bb + (size_t)(ks * 8 + tg) * GSB + wn + ni * 8 + g;
                b[ni][0] = __float_as_uint(p[0]);
                b[ni][1] = __float_as_uint(p[4 * GSB]);
            }
#pragma unroll
            for (int mi = 0; mi < 4; mi++)
#pragma unroll
                for (int ni = 0; ni < 4; ni++)
                    MMA_TF32(acc[mi * 4 + ni], a[mi], b[ni]);
        }
        __syncthreads();
    }

    // epilogue
#pragma unroll
    for (int mi = 0; mi < 4; mi++) {
        int r0 = bm * 128 + wm + mi * 16 + g;
#pragma unroll
        for (int ni = 0; ni < 4; ni++) {
            int c = bn * 128 + wn + ni * 8 + tg * 2;
            float* p = C + (size_t)r0 * N + c;
            float2 v0 = make_float2(acc[mi * 4 + ni][0], acc[mi * 4 + ni][1]);
            float2 v1 = make_float2(acc[mi * 4 + ni][2], acc[mi * 4 + ni][3]);
            *(float2*)p = v0;
            *(float2*)(p + (size_t)8 * N) = v1;
        }
    }
}

#define GEMM_SMEM ((2 * GASZ + 2 * GBSZ) * 4)

// ---------------- per-(node,head) attention coefficients ----------------
__global__ void alphas_kernel(const float* __restrict__ h,
                              const float* __restrict__ a_s, const float* __restrict__ a_d,
                              float* __restrict__ out_s, float* __restrict__ out_d,
                              int H, int C)
{
    int w = (blockIdx.x * blockDim.x + threadIdx.x) >> 5;
    int lane = threadIdx.x & 31;
    if (w >= NNODES * H) return;
    int n = w / H, hd = w % H;
    const float* hp  = h + (size_t)n * H * C + (size_t)hd * C;
    const float* asp = a_s + (size_t)hd * C;
    const float* adp = a_d + (size_t)hd * C;
    float ss = 0.f, sd = 0.f;
    for (int c = lane; c < C; c += 32) {
        float v = hp[c];
        ss += v * asp[c];
        sd += v * adp[c];
    }
#pragma unroll
    for (int o = 16; o; o >>= 1) {
        ss += __shfl_down_sync(0xffffffffu, ss, o);
        sd += __shfl_down_sync(0xffffffffu, sd, o);
    }
    if (lane == 0) { out_s[w] = ss; out_d[w] = sd; }
}

// ---------------- per-(dst,head) segment softmax over incoming edges ----------------
__global__ void softmax_kernel(const int* __restrict__ src,
                               const float* __restrict__ as, const float* __restrict__ ad,
                               float* __restrict__ alpha, int H)
{
    int idx = blockIdx.x * blockDim.x + threadIdx.x;
    if (idx >= NNODES * H) return;
    int d = idx / H, hd = idx % H;
    int s0 = g_off[d], s1 = g_off[d + 1];
    if (s0 == s1) return;
    float adv = ad[idx];

    float m = -1e30f;
    for (int i = s0; i < s1; i++) {
        int e = g_eid[i];
        float x = as[src[e] * H + hd] + adv;
        x = (x > 0.f) ? x : NEG_SLOPE * x;
        m = fmaxf(m, x);
    }
    float sum = 0.f;
    for (int i = s0; i < s1; i++) {
        int e = g_eid[i];
        float x = as[src[e] * H + hd] + adv;
        x = (x > 0.f) ? x : NEG_SLOPE * x;
        float w = __expf(x - m);
        alpha[(size_t)e * H + hd] = w;
        sum += w;
    }
    float inv = 1.f / (sum + EPSV);
    for (int i = s0; i < s1; i++) {
        int e = g_eid[i];
        alpha[(size_t)e * H + hd] *= inv;
    }
}

// ---------------- aggregation ----------------
// out[d, hd*C:] = act( sum_e alpha * h[src] + b ); when do_elu, also tf32-round
// (result feeds the layer-2 tensor-core GEMM).
__global__ void __launch_bounds__(192)
aggregate_kernel(const int* __restrict__ src, const float* __restrict__ alpha,
                 const float* __restrict__ h, float* __restrict__ out,
                 const float* __restrict__ bias, int H, int C, int do_elu)
{
    int d  = blockIdx.x / H;
    int hd = blockIdx.x % H;
    int t  = threadIdx.x;
    int s0 = g_off[d], s1 = g_off[d + 1];
    size_t rs = (size_t)H * C;

    float4 acc = make_float4(0.f, 0.f, 0.f, 0.f);
    for (int i = s0; i < s1; i++) {
        int e = g_eid[i];
        float a = alpha[(size_t)e * H + hd];
        float4 v = *(((const float4*)(h + (size_t)src[e] * rs + (size_t)hd * C)) + t);
        acc.x += a * v.x; acc.y += a * v.y; acc.z += a * v.z; acc.w += a * v.w;
    }
    float4 b = *(((const float4*)(bias + (size_t)hd * C)) + t);
    acc.x += b.x; acc.y += b.y; acc.z += b.z; acc.w += b.w;
    if (do_elu) {
        acc.x = (acc.x > 0.f) ? acc.x : expm1f(acc.x);
        acc.y = (acc.y > 0.f) ? acc.y : expm1f(acc.y);
        acc.z = (acc.z > 0.f) ? acc.z : expm1f(acc.z);
        acc.w = (acc.w > 0.f) ? acc.w : expm1f(acc.w);
        acc.x = tf32r(acc.x); acc.y = tf32r(acc.y);
        acc.z = tf32r(acc.z); acc.w = tf32r(acc.w);
    }
    *(((float4*)(out + (size_t)d * rs + (size_t)hd * C)) + t) = acc;
}

// ---------------- launch ----------------
extern "C" void kernel_launch(void* const* d_in, const int* in_sizes, int n_in,
                              void* d_out, int out_size)
{
    const float* x    = (const float*)d_in[0];
    const float* W1   = (const float*)d_in[1];
    const float* a_s1 = (const float*)d_in[2];
    const float* a_d1 = (const float*)d_in[3];
    const float* b1   = (const float*)d_in[4];
    const float* W2   = (const float*)d_in[5];
    const float* a_s2 = (const float*)d_in[6];
    const float* a_d2 = (const float*)d_in[7];
    const float* b2   = (const float*)d_in[8];
    const int* edges  = (const int*)d_in[9];
    const int* src = edges;
    const int* dst = edges + NEDGES;
    float* out = (float*)d_out;

    float *h1, *o1, *h2, *xr, *w1r, *w2r, *as1, *ad1, *as2, *ad2, *al1, *al2;
    cudaGetSymbolAddress((void**)&h1,  g_h1);
    cudaGetSymbolAddress((void**)&o1,  g_o1);
    cudaGetSymbolAddress((void**)&h2,  g_h2);
    cudaGetSymbolAddress((void**)&xr,  g_xr);
    cudaGetSymbolAddress((void**)&w1r, g_w1r);
    cudaGetSymbolAddress((void**)&w2r, g_w2r);
    cudaGetSymbolAddress((void**)&as1, g_as1);
    cudaGetSymbolAddress((void**)&ad1, g_ad1);
    cudaGetSymbolAddress((void**)&as2, g_as2);
    cudaGetSymbolAddress((void**)&ad2, g_ad2);
    cudaGetSymbolAddress((void**)&al1, g_alpha1);
    cudaGetSymbolAddress((void**)&al2, g_alpha2);

    cudaFuncSetAttribute(tf32_gemm, cudaFuncAttributeMaxDynamicSharedMemorySize, GEMM_SMEM);

    // ---- CSR by destination (shared by both layers) ----
    zero_counts_kernel<<<(NNODES + 255) / 256, 256>>>();
    count_kernel<<<(NEDGES + 255) / 256, 256>>>(dst);
    scan_kernel<<<1, 1024>>>();
    scatter_kernel<<<(NEDGES + 255) / 256, 256>>>(dst);

    // ---- tf32 pre-rounding of GEMM inputs ----
    {
        int n4;
        n4 = (NNODES * DIN) / 4;
        round_tf32_kernel<<<(n4 + 255) / 256, 256>>>(x, xr, n4);
        n4 = (DIN * H1N * DHID) / 4;
        round_tf32_kernel<<<(n4 + 255) / 256, 256>>>(W1, w1r, n4);
        n4 = (H1N * DHID * DHID) / 4;
        round_tf32_kernel<<<(n4 + 255) / 256, 256>>>(W2, w2r, n4);
    }

    // ---- layer 1 ----
    {
        dim3 grid((H1N * DHID) / 128, NNODES / 128);   // (48, 64)
        tf32_gemm<<<grid, 256, GEMM_SMEM>>>(xr, w1r, h1, NNODES, H1N * DHID, DIN);
    }
    {
        int warps = NNODES * H1N;
        alphas_kernel<<<(warps * 32 + 255) / 256, 256>>>(h1, a_s1, a_d1, as1, ad1, H1N, DHID);
    }
    softmax_kernel<<<(NNODES * H1N + 255) / 256, 256>>>(src, as1, ad1, al1, H1N);
    aggregate_kernel<<<NNODES * H1N, DHID / 4>>>(src, al1, h1, o1, b1, H1N, DHID, 1);

    // ---- layer 2 ----
    {
        dim3 grid((H2N * DHID) / 128, NNODES / 128);   // (6, 64)
        tf32_gemm<<<grid, 256, GEMM_SMEM>>>(o1, w2r, h2, NNODES, H2N * DHID, H1N * DHID);
    }
    {
        int warps = NNODES * H2N;
        alphas_kernel<<<(warps * 32 + 255) / 256, 256>>>(h2, a_s2, a_d2, as2, ad2, H2N, DHID);
    }
    softmax_kernel<<<(NNODES * H2N + 255) / 256, 256>>>(src, as2, ad2, al2, H2N);
    aggregate_kernel<<<NNODES * H2N, DHID / 4>>>(src, al2, h2, out, b2, H2N, DHID, 0);
}